// round 15
// baseline (speedup 1.0000x reference)
#include <cuda_runtime.h>
#include <cuda_fp16.h>
#include <cstddef>
#include <cstdint>

// ---------------- problem constants ----------------
constexpr int Nn  = 100000;
constexpr int Mm  = 12500;
constexpr int E0n = 1600000;
constexpr int E1n = 400000;

constexpr int NB0 = (Nn + 1023) / 1024;   // 98
constexpr int NB1 = (Mm + 1023) / 1024;   // 13
constexpr int NBL = (Mm + 1023) / 1024;   // 13
constexpr int TOTB = NB0 + NB1 + NBL;     // 124

constexpr size_t F_N64 = (size_t)Nn * 64;
constexpr size_t F_M64 = (size_t)Mm * 64;
constexpr size_t pad16(size_t x) { return (x + 15) & ~(size_t)15; }

// arena (floats)
constexpr size_t OFF_F1   = 0;
constexpr size_t OFF_F2   = OFF_F1  + F_N64;
constexpr size_t OFF_F21  = OFF_F2  + F_N64;
constexpr size_t OFF_F5   = OFF_F21 + F_N64;
constexpr size_t OFF_F6   = OFF_F5  + F_N64;
constexpr size_t OFF_NP   = OFF_F6  + F_N64;
constexpr size_t OFF_AGG  = OFF_NP  + F_N64;
constexpr size_t OFF_REL  = OFF_AGG + F_N64;
constexpr size_t OFF_MA   = OFF_REL + pad16((size_t)Nn * 3);
constexpr size_t OFF_MB   = OFF_MA  + F_M64;
constexpr size_t OFF_MNP  = OFF_MB  + F_M64;
constexpr size_t OFF_MAGG = OFF_MNP + F_M64;
// int region
constexpr size_t OFF_CNT0  = OFF_MAGG + F_M64;
constexpr size_t OFF_CNT1  = OFF_CNT0  + pad16(Nn);
constexpr size_t OFF_CNTL  = OFF_CNT1  + pad16(Mm);
constexpr size_t OFF_OFFS0 = OFF_CNTL  + pad16(Mm);
constexpr size_t OFF_CUR0  = OFF_OFFS0 + pad16(Nn + 1);
constexpr size_t OFF_CSR0  = OFF_CUR0  + pad16(Nn);
constexpr size_t OFF_OFFS1 = OFF_CSR0  + pad16(E0n);
constexpr size_t OFF_CUR1  = OFF_OFFS1 + pad16(Mm + 1);
constexpr size_t OFF_CSR1  = OFF_CUR1  + pad16(Mm);
constexpr size_t OFF_OFFSL = OFF_CSR1  + pad16(E1n);
constexpr size_t OFF_CURL  = OFF_OFFSL + pad16(Mm + 1);
constexpr size_t OFF_CSRL  = OFF_CURL  + pad16(Mm);
constexpr size_t OFF_BSUM  = OFF_CSRL  + pad16(Nn);
constexpr size_t ARENA_SZ  = OFF_BSUM  + pad16(TOTB);

__device__ __align__(256) static float g_arena[ARENA_SZ];

// ---------------- helpers ----------------
__device__ __forceinline__ void ffma2(unsigned long long& d, unsigned long long a, unsigned long long b) {
    asm("fma.rn.f32x2 %0, %1, %2, %0;" : "+l"(d) : "l"(a), "l"(b));
}
__device__ __forceinline__ float2 up2(unsigned long long x) {
    float2 f;
    asm("mov.b64 {%0, %1}, %2;" : "=f"(f.x), "=f"(f.y) : "l"(x));
    return f;
}
__device__ __forceinline__ unsigned long long dup2(float x) {
    unsigned long long r;
    asm("mov.b64 %0, {%1, %1};" : "=l"(r) : "f"(x));
    return r;
}

// ---------------- CSR build ----------------
__global__ void k_hist(const int2* __restrict__ edges, int* __restrict__ cnt, int E) {
    int e = blockIdx.x * blockDim.x + threadIdx.x;
    if (e < E) atomicAdd(&cnt[edges[e].y], 1);
}
__global__ void k_histL(const int* __restrict__ lab, int* __restrict__ cnt, int n) {
    int i = blockIdx.x * blockDim.x + threadIdx.x;
    if (i < n) atomicAdd(&cnt[lab[i]], 1);
}

__global__ void k_scanA(const int* __restrict__ c0, int* __restrict__ o0,
                        const int* __restrict__ c1, int* __restrict__ o1,
                        const int* __restrict__ c2, int* __restrict__ o2,
                        int* __restrict__ bsum) {
    const int b = blockIdx.x;
    const int* cnt; int* offs; int n; int lb;
    if (b < NB0)            { cnt = c0; offs = o0; n = Nn; lb = b; }
    else if (b < NB0 + NB1) { cnt = c1; offs = o1; n = Mm; lb = b - NB0; }
    else                    { cnt = c2; offs = o2; n = Mm; lb = b - NB0 - NB1; }
    __shared__ int s[1024];
    int t = threadIdx.x;
    int g = lb * 1024 + t;
    int v = (g < n) ? cnt[g] : 0;
    s[t] = v;
    __syncthreads();
    #pragma unroll
    for (int off = 1; off < 1024; off <<= 1) {
        int u = (t >= off) ? s[t - off] : 0;
        __syncthreads();
        s[t] += u;
        __syncthreads();
    }
    if (g < n) offs[g] = s[t] - v;
    if (t == 1023) bsum[b] = s[1023];
}

__global__ void k_scanB(int* __restrict__ bsum, int* __restrict__ o0,
                        int* __restrict__ o1, int* __restrict__ o2) {
    int w = threadIdx.x >> 5, lane = threadIdx.x & 31;
    int base, nb; int* offs; int n;
    if (w == 0)      { base = 0;         nb = NB0; offs = o0; n = Nn; }
    else if (w == 1) { base = NB0;       nb = NB1; offs = o1; n = Mm; }
    else             { base = NB0 + NB1; nb = NBL; offs = o2; n = Mm; }
    int carry = 0;
    for (int i0 = 0; i0 < nb; i0 += 32) {
        int i = i0 + lane;
        int orig = (i < nb) ? bsum[base + i] : 0;
        int v = orig;
        #pragma unroll
        for (int d = 1; d < 32; d <<= 1) {
            int u = __shfl_up_sync(0xffffffffu, v, d);
            if (lane >= d) v += u;
        }
        if (i < nb) bsum[base + i] = carry + v - orig;
        carry += __shfl_sync(0xffffffffu, v, 31);
    }
    if (lane == 0) offs[n] = carry;
}

__global__ void k_scanC(int* __restrict__ o0, int* __restrict__ u0,
                        int* __restrict__ o1, int* __restrict__ u1,
                        int* __restrict__ o2, int* __restrict__ u2,
                        const int* __restrict__ bsum) {
    const int b = blockIdx.x;
    int* offs; int* cur; int n; int lb;
    if (b < NB0)            { offs = o0; cur = u0; n = Nn; lb = b; }
    else if (b < NB0 + NB1) { offs = o1; cur = u1; n = Mm; lb = b - NB0; }
    else                    { offs = o2; cur = u2; n = Mm; lb = b - NB0 - NB1; }
    int g = lb * 1024 + threadIdx.x;
    if (g < n) {
        int val = offs[g] + bsum[b];
        offs[g] = val;
        cur[g]  = val;
    }
}

__global__ void k_scatter(const int2* __restrict__ edges, int* __restrict__ cur,
                          int* __restrict__ csrc, int E) {
    int e = blockIdx.x * blockDim.x + threadIdx.x;
    if (e < E) {
        int2 ed = edges[e];
        int p = atomicAdd(&cur[ed.y], 1);
        csrc[p] = ed.x;
    }
}
__global__ void k_scatterL(const int* __restrict__ lab, int* __restrict__ cur,
                           int* __restrict__ idx, int n) {
    int i = blockIdx.x * blockDim.x + threadIdx.x;
    if (i < n) {
        int p = atomicAdd(&cur[lab[i]], 1);
        idx[p] = i;
    }
}

// ---------------- edge aggregation (fp16 table, direct indices, 8-way MLP) ----------------
__global__ void k_agg(const int* __restrict__ offs, const int* __restrict__ csrc,
                      const float* __restrict__ pos, const unsigned* __restrict__ t2h,
                      const float* __restrict__ Wp, float2* __restrict__ agg, int n) {
    int lane = threadIdx.x & 31;
    int d = (blockIdx.x * blockDim.x + threadIdx.x) >> 5;
    if (d >= n) return;
    int c0 = 2 * lane, c1 = c0 + 1;
    float px = pos[3 * d], py = pos[3 * d + 1], pz = pos[3 * d + 2];
    float pdx = fmaf(px, Wp[c0], fmaf(py, Wp[64 + c0], pz * Wp[128 + c0]));
    float pdy = fmaf(px, Wp[c1], fmaf(py, Wp[64 + c1], pz * Wp[128 + c1]));
    int s0 = offs[d], s1 = offs[d + 1];
    float mx = -3.4e38f, my = -3.4e38f;
    int e = s0;
    for (; e + 8 <= s1; e += 8) {
        int si[8];
        #pragma unroll
        for (int j = 0; j < 8; j++) si[j] = csrc[e + j];
        unsigned u[8];
        #pragma unroll
        for (int j = 0; j < 8; j++) u[j] = t2h[(size_t)si[j] * 32 + lane];
        #pragma unroll
        for (int j = 0; j < 8; j++) {
            float2 v = __half22float2(*reinterpret_cast<__half2*>(&u[j]));
            mx = fmaxf(mx, v.x);
            my = fmaxf(my, v.y);
        }
    }
    for (; e < s1; e++) {
        int s = csrc[e];
        unsigned uu = t2h[(size_t)s * 32 + lane];
        float2 v = __half22float2(*reinterpret_cast<__half2*>(&uu));
        mx = fmaxf(mx, v.x);
        my = fmaxf(my, v.y);
    }
    agg[(size_t)d * 32 + lane] = make_float2(fmaxf(mx - pdx, 0.f), fmaxf(my - pdy, 0.f));
}

// segment sum via label-CSR: warp per cluster
__global__ void k_segsum(const int* __restrict__ offs, const int* __restrict__ idx,
                         const float2* __restrict__ h, float2* __restrict__ c, int m) {
    int lane = threadIdx.x & 31;
    int d = (blockIdx.x * blockDim.x + threadIdx.x) >> 5;
    if (d >= m) return;
    int s0 = offs[d], s1 = offs[d + 1];
    float sx = 0.f, sy = 0.f;
    int e = s0;
    for (; e + 2 <= s1; e += 2) {
        int pa = idx[e], pb = idx[e + 1];
        float2 va = h[(size_t)pa * 32 + lane];
        float2 vb = h[(size_t)pb * 32 + lane];
        sx += va.x + vb.x; sy += va.y + vb.y;
    }
    for (; e < s1; e++) {
        int p = idx[e];
        float2 v = h[(size_t)p * 32 + lane];
        sx += v.x; sy += v.y;
    }
    c[(size_t)d * 32 + lane] = make_float2(sx, sy);
}

// ---------------- unified GEMM kernel (128-row tiles, 8x4 thread tile) ----------------
template<int K1, bool GATHER, bool MAKEREL, bool REL1, int NRES, bool STORE1,
         int FUSE, bool REL2, bool REL2POS, bool RELU2, bool H2OUT>
__global__ __launch_bounds__(256)
void k_gemm(const float* __restrict__ in, const int* __restrict__ gidx,
            const float* __restrict__ points, const float* __restrict__ centers,
            const int* __restrict__ labels, float* __restrict__ relg,
            const float* __restrict__ posv,
            const float* __restrict__ W1, const float* __restrict__ b1,
            const float* __restrict__ res1, const float* __restrict__ res2,
            float* __restrict__ out1,
            const float* __restrict__ W2, const float* __restrict__ Wr2,
            const float* __restrict__ b2,
            void* __restrict__ out2, int n) {
    constexpr int KC = (K1 < 32) ? K1 : 32;
    constexpr int SA_ROWS = (FUSE != 0 && KC < 32) ? 32 : KC;
    constexpr bool NEED_REL = MAKEREL || REL1 || (REL2 && !REL2POS);
    constexpr int RS = 132;

    __shared__ float sW1[K1 * 64];
    __shared__ float sW2[(FUSE == 1) ? 2048 : (FUSE == 2 ? 512 : 1)];
    __shared__ float sA[SA_ROWS * RS];
    __shared__ float sWr1[REL1 ? 384 : 1];
    __shared__ float sWr2[REL2 ? 192 : 1];
    __shared__ float sRel[NEED_REL ? 384 : 1];
    __shared__ float sPos[(REL2 && REL2POS) ? 384 : 1];

    const int tid = threadIdx.x;
    const int tx = tid & 15, ty = tid >> 4;
    const int row0 = blockIdx.x * 128;

    for (int i = tid; i < K1 * 64; i += 256) sW1[i] = W1[i];
    if (REL1) for (int i = tid; i < 192; i += 256) sWr1[i] = W1[K1 * 64 + i];
    if (REL2) for (int i = tid; i < 192; i += 256) sWr2[i] = Wr2[i];
    if (FUSE == 2) for (int i = tid; i < 512; i += 256) sW2[i] = W2[i];

    if (MAKEREL) {
        if (tid < 128) {
            int row = row0 + tid;
            float rx = 0.f, ry = 0.f, rz = 0.f;
            if (row < n) {
                int l = labels[row];
                rx = points[3 * row]     - centers[3 * l];
                ry = points[3 * row + 1] - centers[3 * l + 1];
                rz = points[3 * row + 2] - centers[3 * l + 2];
                relg[3 * row] = rx; relg[3 * row + 1] = ry; relg[3 * row + 2] = rz;
            }
            sRel[tid * 3] = rx; sRel[tid * 3 + 1] = ry; sRel[tid * 3 + 2] = rz;
        }
    } else if (NEED_REL) {
        if (tid < 128) {
            int row = row0 + tid;
            float rx = 0.f, ry = 0.f, rz = 0.f;
            if (row < n) { rx = relg[3 * row]; ry = relg[3 * row + 1]; rz = relg[3 * row + 2]; }
            sRel[tid * 3] = rx; sRel[tid * 3 + 1] = ry; sRel[tid * 3 + 2] = rz;
        }
    }
    if (REL2 && REL2POS) {
        if (tid >= 128) {
            int r = tid - 128;
            int row = row0 + r;
            float rx = 0.f, ry = 0.f, rz = 0.f;
            if (row < n) { rx = posv[3 * row]; ry = posv[3 * row + 1]; rz = posv[3 * row + 2]; }
            sPos[r * 3] = rx; sPos[r * 3 + 1] = ry; sPos[r * 3 + 2] = rz;
        }
    }

    unsigned long long acc[8][2];
    #pragma unroll
    for (int r = 0; r < 8; r++) { acc[r][0] = 0ULL; acc[r][1] = 0ULL; }

    // ---- first GEMM, A chunked over K ----
    for (int kc = 0; kc < K1; kc += KC) {
        if (kc > 0) __syncthreads();
        for (int i = tid; i < KC * 128; i += 256) {
            int r = i / KC, k = i - r * KC;
            int row = row0 + r;
            float v = 0.f;
            if (row < n) {
                int sr = GATHER ? gidx[row] : row;
                v = in[(size_t)sr * K1 + kc + k];
            }
            sA[k * RS + r] = v;
        }
        __syncthreads();
        #pragma unroll 8
        for (int k = 0; k < KC; k++) {
            const float4 av0 = *reinterpret_cast<const float4*>(&sA[k * RS + ty * 8]);
            const float4 av1 = *reinterpret_cast<const float4*>(&sA[k * RS + ty * 8 + 4]);
            const ulonglong2 bv = *reinterpret_cast<const ulonglong2*>(&sW1[(kc + k) * 64 + tx * 4]);
            unsigned long long a0 = dup2(av0.x), a1 = dup2(av0.y), a2 = dup2(av0.z), a3 = dup2(av0.w);
            unsigned long long a4 = dup2(av1.x), a5 = dup2(av1.y), a6 = dup2(av1.z), a7 = dup2(av1.w);
            ffma2(acc[0][0], a0, bv.x); ffma2(acc[0][1], a0, bv.y);
            ffma2(acc[1][0], a1, bv.x); ffma2(acc[1][1], a1, bv.y);
            ffma2(acc[2][0], a2, bv.x); ffma2(acc[2][1], a2, bv.y);
            ffma2(acc[3][0], a3, bv.x); ffma2(acc[3][1], a3, bv.y);
            ffma2(acc[4][0], a4, bv.x); ffma2(acc[4][1], a4, bv.y);
            ffma2(acc[5][0], a5, bv.x); ffma2(acc[5][1], a5, bv.y);
            ffma2(acc[6][0], a6, bv.x); ffma2(acc[6][1], a6, bv.y);
            ffma2(acc[7][0], a7, bv.x); ffma2(acc[7][1], a7, bv.y);
        }
    }

    // ---- epilogue 1 ----
    float v[8][4];
    const float b1x = b1[tx * 4], b1y = b1[tx * 4 + 1], b1z = b1[tx * 4 + 2], b1w = b1[tx * 4 + 3];
    #pragma unroll
    for (int r = 0; r < 8; r++) {
        float2 p0 = up2(acc[r][0]), p1 = up2(acc[r][1]);
        v[r][0] = p0.x + b1x; v[r][1] = p0.y + b1y;
        v[r][2] = p1.x + b1z; v[r][3] = p1.y + b1w;
        if (REL1) {
            int lr = ty * 8 + r;
            float rx = sRel[lr * 3], ry = sRel[lr * 3 + 1], rz = sRel[lr * 3 + 2];
            #pragma unroll
            for (int c = 0; c < 4; c++) {
                int col = tx * 4 + c;
                v[r][c] += rx * sWr1[col] + ry * sWr1[64 + col] + rz * sWr1[128 + col];
            }
        }
        #pragma unroll
        for (int c = 0; c < 4; c++) v[r][c] = fmaxf(v[r][c], 0.f);
        int row = row0 + ty * 8 + r;
        if (row < n) {
            size_t base = (size_t)row * 64 + tx * 4;
            if (NRES >= 1) {
                const float4 r1 = *reinterpret_cast<const float4*>(&res1[base]);
                v[r][0] += r1.x; v[r][1] += r1.y; v[r][2] += r1.z; v[r][3] += r1.w;
            }
            if (NRES >= 2) {
                const float4 r2 = *reinterpret_cast<const float4*>(&res2[base]);
                v[r][0] += r2.x; v[r][1] += r2.y; v[r][2] += r2.z; v[r][3] += r2.w;
            }
            if (STORE1) {
                float4 o = { v[r][0], v[r][1], v[r][2], v[r][3] };
                *reinterpret_cast<float4*>(&out1[base]) = o;
            }
        } else {
            v[r][0] = v[r][1] = v[r][2] = v[r][3] = 0.f;
        }
    }

    if (FUSE == 0) return;

    // ---- second GEMM: input = out1 tile (registers v), halves; W2 streamed per half ----
    unsigned long long acc2[8][2];
    float accc[4];
    if (FUSE == 1) {
        #pragma unroll
        for (int r = 0; r < 8; r++) { acc2[r][0] = 0ULL; acc2[r][1] = 0ULL; }
    } else {
        accc[0] = b2[tid & 7]; accc[1] = accc[0]; accc[2] = accc[0]; accc[3] = accc[0];
    }

    #pragma unroll
    for (int half = 0; half < 2; half++) {
        __syncthreads();
        if (FUSE == 1)
            for (int i = tid; i < 2048; i += 256) sW2[i] = W2[half * 2048 + i];
        if ((tx >> 3) == half) {
            #pragma unroll
            for (int c = 0; c < 4; c++)
                #pragma unroll
                for (int r = 0; r < 8; r++)
                    sA[(tx * 4 + c - half * 32) * RS + (ty * 8 + r)] = v[r][c];
        }
        __syncthreads();
        if (FUSE == 1) {
            #pragma unroll 8
            for (int k = 0; k < 32; k++) {
                const float4 av0 = *reinterpret_cast<const float4*>(&sA[k * RS + ty * 8]);
                const float4 av1 = *reinterpret_cast<const float4*>(&sA[k * RS + ty * 8 + 4]);
                const ulonglong2 bv = *reinterpret_cast<const ulonglong2*>(&sW2[k * 64 + tx * 4]);
                unsigned long long a0 = dup2(av0.x), a1 = dup2(av0.y), a2 = dup2(av0.z), a3 = dup2(av0.w);
                unsigned long long a4 = dup2(av1.x), a5 = dup2(av1.y), a6 = dup2(av1.z), a7 = dup2(av1.w);
                ffma2(acc2[0][0], a0, bv.x); ffma2(acc2[0][1], a0, bv.y);
                ffma2(acc2[1][0], a1, bv.x); ffma2(acc2[1][1], a1, bv.y);
                ffma2(acc2[2][0], a2, bv.x); ffma2(acc2[2][1], a2, bv.y);
                ffma2(acc2[3][0], a3, bv.x); ffma2(acc2[3][1], a3, bv.y);
                ffma2(acc2[4][0], a4, bv.x); ffma2(acc2[4][1], a4, bv.y);
                ffma2(acc2[5][0], a5, bv.x); ffma2(acc2[5][1], a5, bv.y);
                ffma2(acc2[6][0], a6, bv.x); ffma2(acc2[6][1], a6, bv.y);
                ffma2(acc2[7][0], a7, bv.x); ffma2(acc2[7][1], a7, bv.y);
            }
        } else {
            int r8 = tid >> 3, cls = tid & 7;
            #pragma unroll
            for (int h = 0; h < 4; h++) {
                int lr = r8 + h * 32;
                float a = accc[h];
                #pragma unroll 16
                for (int k = 0; k < 32; k++)
                    a = fmaf(sA[k * RS + lr], sW2[(half * 32 + k) * 8 + cls], a);
                accc[h] = a;
            }
        }
    }

    if (FUSE == 1) {
        const float b2x = b2[tx * 4], b2y = b2[tx * 4 + 1], b2z = b2[tx * 4 + 2], b2w = b2[tx * 4 + 3];
        #pragma unroll
        for (int r = 0; r < 8; r++) {
            int row = row0 + ty * 8 + r;
            if (row >= n) continue;
            float2 p0 = up2(acc2[r][0]), p1 = up2(acc2[r][1]);
            float w0 = p0.x + b2x, w1 = p0.y + b2y, w2 = p1.x + b2z, w3 = p1.y + b2w;
            if (REL2) {
                int lr = ty * 8 + r;
                const float* sv = REL2POS ? sPos : sRel;
                float rx = sv[lr * 3], ry = sv[lr * 3 + 1], rz = sv[lr * 3 + 2];
                int col = tx * 4;
                w0 += rx * sWr2[col]     + ry * sWr2[64 + col]     + rz * sWr2[128 + col];
                w1 += rx * sWr2[col + 1] + ry * sWr2[64 + col + 1] + rz * sWr2[128 + col + 1];
                w2 += rx * sWr2[col + 2] + ry * sWr2[64 + col + 2] + rz * sWr2[128 + col + 2];
                w3 += rx * sWr2[col + 3] + ry * sWr2[64 + col + 3] + rz * sWr2[128 + col + 3];
            }
            if (RELU2) {
                w0 = fmaxf(w0, 0.f); w1 = fmaxf(w1, 0.f);
                w2 = fmaxf(w2, 0.f); w3 = fmaxf(w3, 0.f);
            }
            if (H2OUT) {
                __half2 h0 = __floats2half2_rn(w0, w1);
                __half2 h1 = __floats2half2_rn(w2, w3);
                uint2 o;
                o.x = *reinterpret_cast<unsigned*>(&h0);
                o.y = *reinterpret_cast<unsigned*>(&h1);
                reinterpret_cast<uint2*>(out2)[(size_t)row * 16 + tx] = o;
            } else {
                float4 o = { w0, w1, w2, w3 };
                *reinterpret_cast<float4*>(reinterpret_cast<float*>(out2) + (size_t)row * 64 + tx * 4) = o;
            }
        }
    } else {
        int r8 = tid >> 3, cls = tid & 7;
        #pragma unroll
        for (int h = 0; h < 4; h++) {
            int row = row0 + r8 + h * 32;
            if (row < n) reinterpret_cast<float*>(out2)[(size_t)row * 8 + cls] = accc[h];
        }
    }
}

// ---------------- host orchestration ----------------

extern "C" void kernel_launch(void* const* d_in, const int* in_sizes, int n_in,
                              void* d_out, int out_size) {
    (void)in_sizes; (void)n_in; (void)out_size;
    float* A = nullptr;
    cudaGetSymbolAddress((void**)&A, g_arena);

    // one-time stream/event creation (first call is the eager correctness run,
    // so creation never happens during graph capture)
    static cudaStream_t s2 = nullptr;
    static cudaEvent_t evFork = nullptr, evJoin = nullptr;
    if (!s2) {
        cudaStreamCreateWithFlags(&s2, cudaStreamNonBlocking);
        cudaEventCreateWithFlags(&evFork, cudaEventDisableTiming);
        cudaEventCreateWithFlags(&evJoin, cudaEventDisableTiming);
    }

    float* f1   = A + OFF_F1;
    float* f2   = A + OFF_F2;
    float* f21  = A + OFF_F21;
    float* f5   = A + OFF_F5;
    float* f6   = A + OFF_F6;
    float* np   = A + OFF_NP;
    float* agg  = A + OFF_AGG;
    float* rel  = A + OFF_REL;
    float* mA   = A + OFF_MA;
    float* mB   = A + OFF_MB;
    float* mnp  = A + OFF_MNP;
    float* magg = A + OFF_MAGG;
    int* cnt0  = (int*)(A + OFF_CNT0);
    int* cnt1  = (int*)(A + OFF_CNT1);
    int* cntL  = (int*)(A + OFF_CNTL);
    int* offs0 = (int*)(A + OFF_OFFS0);
    int* cur0  = (int*)(A + OFF_CUR0);
    int* csr0  = (int*)(A + OFF_CSR0);
    int* offs1 = (int*)(A + OFF_OFFS1);
    int* cur1  = (int*)(A + OFF_CUR1);
    int* csr1  = (int*)(A + OFF_CSR1);
    int* offsL = (int*)(A + OFF_OFFSL);
    int* curL  = (int*)(A + OFF_CURL);
    int* csrL  = (int*)(A + OFF_CSRL);
    int* bsum  = (int*)(A + OFF_BSUM);

    const float* features = (const float*)d_in[0];
    const float* points   = (const float*)d_in[1];
    const float* centers  = (const float*)d_in[2];
    const int*   l0       = (const int*)d_in[3];
    const int*   l1       = (const int*)d_in[4];
    const int*   labels   = (const int*)d_in[5];
    const float* W_fe     = (const float*)d_in[6];
    const float* b_fe     = (const float*)d_in[7];
    const float* mini_We  = (const float*)d_in[8];
    const float* mini_be  = (const float*)d_in[9];
    const float* mini_Wu  = (const float*)d_in[10];
    const float* mini_bu  = (const float*)d_in[11];
    const float* W_m1     = (const float*)d_in[12];
    const float* b_m1     = (const float*)d_in[13];
    const float* W_m2     = (const float*)d_in[14];
    const float* b_m2     = (const float*)d_in[15];
    const float* gnn_We   = (const float*)d_in[16];
    const float* gnn_be   = (const float*)d_in[17];
    const float* gnn_Wu   = (const float*)d_in[18];
    const float* gnn_bu   = (const float*)d_in[19];
    const float* W_l      = (const float*)d_in[20];
    const float* b_l      = (const float*)d_in[21];
    const float* W_c      = (const float*)d_in[22];
    const float* b_c      = (const float*)d_in[23];
    float* out = (float*)d_out;

    const int TN = (Nn + 127) / 128;   // 782
    const int TM = (Mm + 127) / 128;   // 98

    const float* We0 = mini_We;               const float* be0 = mini_be;
    const float* We1 = mini_We + 67 * 64;     const float* be1 = mini_be + 64;
    const float* We2 = mini_We + 2 * 67 * 64; const float* be2 = mini_be + 128;
    const float* We3 = mini_We + 3 * 67 * 64; const float* be3 = mini_be + 192;
    const float* Wu0 = mini_Wu;               const float* bu0 = mini_bu;
    const float* Wu1 = mini_Wu + 4096;        const float* bu1 = mini_bu + 64;
    const float* Wu2 = mini_Wu + 2 * 4096;    const float* bu2 = mini_bu + 128;
    const float* Wu3 = mini_Wu + 3 * 4096;    const float* bu3 = mini_bu + 192;
    const float* gWe0 = gnn_We;               const float* gbe0 = gnn_be;
    const float* gWe1 = gnn_We + 67 * 64;     const float* gbe1 = gnn_be + 64;
    const float* gWu0 = gnn_Wu;               const float* gbu0 = gnn_bu;
    const float* gWu1 = gnn_Wu + 4096;        const float* gbu1 = gnn_bu + 64;

    // ---- fork: CSR build on s2, f1 GEMM on main stream ----
    cudaEventRecord(evFork, 0);
    cudaStreamWaitEvent(s2, evFork, 0);

    cudaMemsetAsync((void*)cnt0, 0, (OFF_OFFS0 - OFF_CNT0) * sizeof(float), s2);
    k_hist<<<(E0n + 255) / 256, 256, 0, s2>>>((const int2*)l0, cnt0, E0n);
    k_hist<<<(E1n + 255) / 256, 256, 0, s2>>>((const int2*)l1, cnt1, E1n);
    k_histL<<<(Nn + 255) / 256, 256, 0, s2>>>(labels, cntL, Nn);
    k_scanA<<<TOTB, 1024, 0, s2>>>(cnt0, offs0, cnt1, offs1, cntL, offsL, bsum);
    k_scanB<<<1, 96, 0, s2>>>(bsum, offs0, offs1, offsL);
    k_scanC<<<TOTB, 1024, 0, s2>>>(offs0, cur0, offs1, cur1, offsL, curL, bsum);
    k_scatter<<<(E0n + 255) / 256, 256, 0, s2>>>((const int2*)l0, cur0, csr0, E0n);
    k_scatter<<<(E1n + 255) / 256, 256, 0, s2>>>((const int2*)l1, cur1, csr1, E1n);
    k_scatterL<<<(Nn + 255) / 256, 256, 0, s2>>>(labels, curL, csrL, Nn);
    cudaEventRecord(evJoin, s2);

    // main stream: f1 = relu([feat,rel]@W_fe+b) ; t0(half) fused (independent of CSR)
    k_gemm<4, false, true, true, 0, true, 1, true, true, false, true><<<TN, 256>>>(
        features, nullptr, points, centers, labels, rel, points,
        W_fe, b_fe, nullptr, nullptr, f1, We0 + 192, We0, be0, np, Nn);

    // join: everything below needs the CSR structures
    cudaStreamWaitEvent(0, evJoin, 0);

    // ---- GNN layer 0 on N ----
    k_agg<<<(Nn + 7) / 8, 256>>>(offs0, csr0, points, (const unsigned*)np, We0, (float2*)agg, Nn);
    k_gemm<64, false, false, false, 1, true, 1, true, true, false, true><<<TN, 256>>>(
        agg, nullptr, nullptr, nullptr, nullptr, rel, points,
        Wu0, bu0, f1, nullptr, f2, We1 + 192, We1, be1, np, Nn);   // f2 ; t1(half)

    // ---- GNN layer 1 on N, fused with h = relu([f21,rel]@W_m1+b_m1) (h fp32) ----
    k_agg<<<(Nn + 7) / 8, 256>>>(offs0, csr0, points, (const unsigned*)np, We1, (float2*)agg, Nn);
    k_gemm<64, false, false, false, 1, true, 1, true, false, true, false><<<TN, 256>>>(
        agg, nullptr, nullptr, nullptr, nullptr, rel, nullptr,
        Wu1, bu1, f2, nullptr, f21, W_m1, W_m1 + 4096, b_m1, np, Nn);   // f21 ; h (fp32)

    // ---- cluster branch ----
    k_segsum<<<(Mm + 7) / 8, 256>>>(offsL, csrL, (const float2*)np, (float2*)mA, Mm);
    k_gemm<64, false, false, false, 0, true, 1, true, true, false, true><<<TM, 256>>>(
        mA, nullptr, nullptr, nullptr, nullptr, rel, centers,
        W_m2, b_m2, nullptr, nullptr, mB, gWe0 + 192, gWe0, gbe0, mnp, Mm);   // f3 ; tM0(half)
    k_agg<<<(Mm + 7) / 8, 256>>>(offs1, csr1, centers, (const unsigned*)mnp, gWe0, (float2*)magg, Mm);
    k_gemm<64, false, false, false, 1, true, 1, true, true, false, true><<<TM, 256>>>(
        magg, nullptr, nullptr, nullptr, nullptr, rel, centers,
        gWu0, gbu0, mB, nullptr, mA, gWe1 + 192, gWe1, gbe1, mnp, Mm);        // f4 ; tM1(half)
    k_agg<<<(Mm + 7) / 8, 256>>>(offs1, csr1, centers, (const unsigned*)mnp, gWe1, (float2*)magg, Mm);
    k_gemm<64, false, false, false, 1, true, 0, false, false, false, false><<<TM, 256>>>(
        magg, nullptr, nullptr, nullptr, nullptr, rel, nullptr,
        gWu1, gbu1, mA, nullptr, mB, nullptr, nullptr, nullptr, nullptr, Mm); // f4_1

    // ---- f5 = relu([f4_1[labels], rel]@W_l+b_l) ; t2(half) fused ----
    k_gemm<64, true, false, true, 0, true, 1, true, true, false, true><<<TN, 256>>>(
        mB, labels, nullptr, nullptr, nullptr, rel, points,
        W_l, b_l, nullptr, nullptr, f5, We2 + 192, We2, be2, np, Nn);

    // ---- GNN layer 2 on N: f6 = relu(agg@Wu2+bu2)+f5+f21 ; t3(half) fused ----
    k_agg<<<(Nn + 7) / 8, 256>>>(offs0, csr0, points, (const unsigned*)np, We2, (float2*)agg, Nn);
    k_gemm<64, false, false, false, 2, true, 1, true, true, false, true><<<TN, 256>>>(
        agg, nullptr, nullptr, nullptr, nullptr, rel, points,
        Wu2, bu2, f5, f21, f6, We3 + 192, We3, be3, np, Nn);

    // ---- GNN layer 3 on N fused with classifier ----
    k_agg<<<(Nn + 7) / 8, 256>>>(offs0, csr0, points, (const unsigned*)np, We3, (float2*)agg, Nn);
    k_gemm<64, false, false, false, 2, false, 2, false, false, false, false><<<TN, 256>>>(
        agg, nullptr, nullptr, nullptr, nullptr, rel, nullptr,
        Wu3, bu3, f6, f2, nullptr, W_c, nullptr, b_c, out, Nn);
}

// round 16
// speedup vs baseline: 1.0208x; 1.0208x over previous
#include <cuda_runtime.h>
#include <cuda_fp16.h>
#include <cstddef>
#include <cstdint>

// ---------------- problem constants ----------------
constexpr int Nn  = 100000;
constexpr int Mm  = 12500;
constexpr int E0n = 1600000;
constexpr int E1n = 400000;

constexpr int NB0 = (Nn + 1023) / 1024;   // 98
constexpr int NB1 = (Mm + 1023) / 1024;   // 13
constexpr int NBL = (Mm + 1023) / 1024;   // 13
constexpr int TOTB = NB0 + NB1 + NBL;     // 124

constexpr size_t F_N64 = (size_t)Nn * 64;
constexpr size_t F_M64 = (size_t)Mm * 64;
constexpr size_t pad16(size_t x) { return (x + 15) & ~(size_t)15; }

// arena (floats)
constexpr size_t OFF_F1   = 0;
constexpr size_t OFF_F2   = OFF_F1  + F_N64;
constexpr size_t OFF_F21  = OFF_F2  + F_N64;
constexpr size_t OFF_F5   = OFF_F21 + F_N64;
constexpr size_t OFF_F6   = OFF_F5  + F_N64;
constexpr size_t OFF_NP   = OFF_F6  + F_N64;
constexpr size_t OFF_AGG  = OFF_NP  + F_N64;
constexpr size_t OFF_REL  = OFF_AGG + F_N64;
constexpr size_t OFF_MA   = OFF_REL + pad16((size_t)Nn * 3);
constexpr size_t OFF_MB   = OFF_MA  + F_M64;
constexpr size_t OFF_MNP  = OFF_MB  + F_M64;
constexpr size_t OFF_MAGG = OFF_MNP + F_M64;
// int region
constexpr size_t OFF_CNT0  = OFF_MAGG + F_M64;
constexpr size_t OFF_CNT1  = OFF_CNT0  + pad16(Nn);
constexpr size_t OFF_CNTL  = OFF_CNT1  + pad16(Mm);
constexpr size_t OFF_OFFS0 = OFF_CNTL  + pad16(Mm);
constexpr size_t OFF_CUR0  = OFF_OFFS0 + pad16(Nn + 1);
constexpr size_t OFF_CSR0  = OFF_CUR0  + pad16(Nn);
constexpr size_t OFF_OFFS1 = OFF_CSR0  + pad16(E0n);
constexpr size_t OFF_CUR1  = OFF_OFFS1 + pad16(Mm + 1);
constexpr size_t OFF_CSR1  = OFF_CUR1  + pad16(Mm);
constexpr size_t OFF_OFFSL = OFF_CSR1  + pad16(E1n);
constexpr size_t OFF_CURL  = OFF_OFFSL + pad16(Mm + 1);
constexpr size_t OFF_CSRL  = OFF_CURL  + pad16(Mm);
constexpr size_t OFF_BSUM  = OFF_CSRL  + pad16(Nn);
constexpr size_t ARENA_SZ  = OFF_BSUM  + pad16(TOTB);

__device__ __align__(256) static float g_arena[ARENA_SZ];

// ---------------- helpers ----------------
__device__ __forceinline__ void ffma2(unsigned long long& d, unsigned long long a, unsigned long long b) {
    asm("fma.rn.f32x2 %0, %1, %2, %0;" : "+l"(d) : "l"(a), "l"(b));
}
__device__ __forceinline__ float2 up2(unsigned long long x) {
    float2 f;
    asm("mov.b64 {%0, %1}, %2;" : "=f"(f.x), "=f"(f.y) : "l"(x));
    return f;
}
__device__ __forceinline__ unsigned long long dup2(float x) {
    unsigned long long r;
    asm("mov.b64 %0, {%1, %1};" : "=l"(r) : "f"(x));
    return r;
}

// ---------------- CSR build ----------------
__global__ void k_hist(const int2* __restrict__ edges, int* __restrict__ cnt, int E) {
    int e = blockIdx.x * blockDim.x + threadIdx.x;
    if (e < E) atomicAdd(&cnt[edges[e].y], 1);
}
__global__ void k_histL(const int* __restrict__ lab, int* __restrict__ cnt, int n) {
    int i = blockIdx.x * blockDim.x + threadIdx.x;
    if (i < n) atomicAdd(&cnt[lab[i]], 1);
}

__global__ void k_scanA(const int* __restrict__ c0, int* __restrict__ o0,
                        const int* __restrict__ c1, int* __restrict__ o1,
                        const int* __restrict__ c2, int* __restrict__ o2,
                        int* __restrict__ bsum) {
    const int b = blockIdx.x;
    const int* cnt; int* offs; int n; int lb;
    if (b < NB0)            { cnt = c0; offs = o0; n = Nn; lb = b; }
    else if (b < NB0 + NB1) { cnt = c1; offs = o1; n = Mm; lb = b - NB0; }
    else                    { cnt = c2; offs = o2; n = Mm; lb = b - NB0 - NB1; }
    __shared__ int s[1024];
    int t = threadIdx.x;
    int g = lb * 1024 + t;
    int v = (g < n) ? cnt[g] : 0;
    s[t] = v;
    __syncthreads();
    #pragma unroll
    for (int off = 1; off < 1024; off <<= 1) {
        int u = (t >= off) ? s[t - off] : 0;
        __syncthreads();
        s[t] += u;
        __syncthreads();
    }
    if (g < n) offs[g] = s[t] - v;
    if (t == 1023) bsum[b] = s[1023];
}

__global__ void k_scanB(int* __restrict__ bsum, int* __restrict__ o0,
                        int* __restrict__ o1, int* __restrict__ o2) {
    int w = threadIdx.x >> 5, lane = threadIdx.x & 31;
    int base, nb; int* offs; int n;
    if (w == 0)      { base = 0;         nb = NB0; offs = o0; n = Nn; }
    else if (w == 1) { base = NB0;       nb = NB1; offs = o1; n = Mm; }
    else             { base = NB0 + NB1; nb = NBL; offs = o2; n = Mm; }
    int carry = 0;
    for (int i0 = 0; i0 < nb; i0 += 32) {
        int i = i0 + lane;
        int orig = (i < nb) ? bsum[base + i] : 0;
        int v = orig;
        #pragma unroll
        for (int d = 1; d < 32; d <<= 1) {
            int u = __shfl_up_sync(0xffffffffu, v, d);
            if (lane >= d) v += u;
        }
        if (i < nb) bsum[base + i] = carry + v - orig;
        carry += __shfl_sync(0xffffffffu, v, 31);
    }
    if (lane == 0) offs[n] = carry;
}

__global__ void k_scanC(int* __restrict__ o0, int* __restrict__ u0,
                        int* __restrict__ o1, int* __restrict__ u1,
                        int* __restrict__ o2, int* __restrict__ u2,
                        const int* __restrict__ bsum) {
    const int b = blockIdx.x;
    int* offs; int* cur; int n; int lb;
    if (b < NB0)            { offs = o0; cur = u0; n = Nn; lb = b; }
    else if (b < NB0 + NB1) { offs = o1; cur = u1; n = Mm; lb = b - NB0; }
    else                    { offs = o2; cur = u2; n = Mm; lb = b - NB0 - NB1; }
    int g = lb * 1024 + threadIdx.x;
    if (g < n) {
        int val = offs[g] + bsum[b];
        offs[g] = val;
        cur[g]  = val;
    }
}

__global__ void k_scatter(const int2* __restrict__ edges, int* __restrict__ cur,
                          int* __restrict__ csrc, int E) {
    int e = blockIdx.x * blockDim.x + threadIdx.x;
    if (e < E) {
        int2 ed = edges[e];
        int p = atomicAdd(&cur[ed.y], 1);
        csrc[p] = ed.x;
    }
}
__global__ void k_scatterL(const int* __restrict__ lab, int* __restrict__ cur,
                           int* __restrict__ idx, int n) {
    int i = blockIdx.x * blockDim.x + threadIdx.x;
    if (i < n) {
        int p = atomicAdd(&cur[lab[i]], 1);
        idx[p] = i;
    }
}

// ---------------- edge aggregation (fp16 table, direct indices, 8-way MLP) ----------------
__global__ void k_agg(const int* __restrict__ offs, const int* __restrict__ csrc,
                      const float* __restrict__ pos, const unsigned* __restrict__ t2h,
                      const float* __restrict__ Wp, float2* __restrict__ agg, int n) {
    int lane = threadIdx.x & 31;
    int d = (blockIdx.x * blockDim.x + threadIdx.x) >> 5;
    if (d >= n) return;
    int c0 = 2 * lane, c1 = c0 + 1;
    float px = pos[3 * d], py = pos[3 * d + 1], pz = pos[3 * d + 2];
    float pdx = fmaf(px, Wp[c0], fmaf(py, Wp[64 + c0], pz * Wp[128 + c0]));
    float pdy = fmaf(px, Wp[c1], fmaf(py, Wp[64 + c1], pz * Wp[128 + c1]));
    int s0 = offs[d], s1 = offs[d + 1];
    float mx = -3.4e38f, my = -3.4e38f;
    int e = s0;
    for (; e + 8 <= s1; e += 8) {
        int si[8];
        #pragma unroll
        for (int j = 0; j < 8; j++) si[j] = csrc[e + j];
        unsigned u[8];
        #pragma unroll
        for (int j = 0; j < 8; j++) u[j] = t2h[(size_t)si[j] * 32 + lane];
        #pragma unroll
        for (int j = 0; j < 8; j++) {
            float2 v = __half22float2(*reinterpret_cast<__half2*>(&u[j]));
            mx = fmaxf(mx, v.x);
            my = fmaxf(my, v.y);
        }
    }
    for (; e < s1; e++) {
        int s = csrc[e];
        unsigned uu = t2h[(size_t)s * 32 + lane];
        float2 v = __half22float2(*reinterpret_cast<__half2*>(&uu));
        mx = fmaxf(mx, v.x);
        my = fmaxf(my, v.y);
    }
    agg[(size_t)d * 32 + lane] = make_float2(fmaxf(mx - pdx, 0.f), fmaxf(my - pdy, 0.f));
}

// segment sum via label-CSR: warp per cluster
__global__ void k_segsum(const int* __restrict__ offs, const int* __restrict__ idx,
                         const float2* __restrict__ h, float2* __restrict__ c, int m) {
    int lane = threadIdx.x & 31;
    int d = (blockIdx.x * blockDim.x + threadIdx.x) >> 5;
    if (d >= m) return;
    int s0 = offs[d], s1 = offs[d + 1];
    float sx = 0.f, sy = 0.f;
    int e = s0;
    for (; e + 2 <= s1; e += 2) {
        int pa = idx[e], pb = idx[e + 1];
        float2 va = h[(size_t)pa * 32 + lane];
        float2 vb = h[(size_t)pb * 32 + lane];
        sx += va.x + vb.x; sy += va.y + vb.y;
    }
    for (; e < s1; e++) {
        int p = idx[e];
        float2 v = h[(size_t)p * 32 + lane];
        sx += v.x; sy += v.y;
    }
    c[(size_t)d * 32 + lane] = make_float2(sx, sy);
}

// ---------------- unified GEMM kernel (128-row tiles, single-pass smem) ----------------
// sA lives in opt-in dynamic smem: 64 k-rows x 132 floats (33792 B)
template<int K1, bool GATHER, bool MAKEREL, bool REL1, int NRES, bool STORE1,
         int FUSE, bool REL2, bool REL2POS, bool RELU2, bool H2OUT>
__global__ __launch_bounds__(256)
void k_gemm(const float* __restrict__ in, const int* __restrict__ gidx,
            const float* __restrict__ points, const float* __restrict__ centers,
            const int* __restrict__ labels, float* __restrict__ relg,
            const float* __restrict__ posv,
            const float* __restrict__ W1, const float* __restrict__ b1,
            const float* __restrict__ res1, const float* __restrict__ res2,
            float* __restrict__ out1,
            const float* __restrict__ W2, const float* __restrict__ Wr2,
            const float* __restrict__ b2,
            void* __restrict__ out2, int n) {
    constexpr bool NEED_REL = MAKEREL || REL1 || (REL2 && !REL2POS);
    constexpr int RS = 132;

    extern __shared__ float sA[];   // [max(K1, FUSE?64) rows][RS]
    __shared__ float sW1[K1 * 64];
    __shared__ float sW2[(FUSE == 1) ? 4096 : (FUSE == 2 ? 512 : 1)];
    __shared__ float sWr1[REL1 ? 384 : 1];
    __shared__ float sWr2[REL2 ? 192 : 1];
    __shared__ float sRel[NEED_REL ? 384 : 1];
    __shared__ float sPos[(REL2 && REL2POS) ? 384 : 1];

    const int tid = threadIdx.x;
    const int tx = tid & 15, ty = tid >> 4;
    const int row0 = blockIdx.x * 128;

    for (int i = tid; i < K1 * 64; i += 256) sW1[i] = W1[i];
    if (REL1) for (int i = tid; i < 192; i += 256) sWr1[i] = W1[K1 * 64 + i];
    if (REL2) for (int i = tid; i < 192; i += 256) sWr2[i] = Wr2[i];
    if (FUSE == 2) for (int i = tid; i < 512; i += 256) sW2[i] = W2[i];

    if (MAKEREL) {
        if (tid < 128) {
            int row = row0 + tid;
            float rx = 0.f, ry = 0.f, rz = 0.f;
            if (row < n) {
                int l = labels[row];
                rx = points[3 * row]     - centers[3 * l];
                ry = points[3 * row + 1] - centers[3 * l + 1];
                rz = points[3 * row + 2] - centers[3 * l + 2];
                relg[3 * row] = rx; relg[3 * row + 1] = ry; relg[3 * row + 2] = rz;
            }
            sRel[tid * 3] = rx; sRel[tid * 3 + 1] = ry; sRel[tid * 3 + 2] = rz;
        }
    } else if (NEED_REL) {
        if (tid < 128) {
            int row = row0 + tid;
            float rx = 0.f, ry = 0.f, rz = 0.f;
            if (row < n) { rx = relg[3 * row]; ry = relg[3 * row + 1]; rz = relg[3 * row + 2]; }
            sRel[tid * 3] = rx; sRel[tid * 3 + 1] = ry; sRel[tid * 3 + 2] = rz;
        }
    }
    if (REL2 && REL2POS) {
        if (tid >= 128) {
            int r = tid - 128;
            int row = row0 + r;
            float rx = 0.f, ry = 0.f, rz = 0.f;
            if (row < n) { rx = posv[3 * row]; ry = posv[3 * row + 1]; rz = posv[3 * row + 2]; }
            sPos[r * 3] = rx; sPos[r * 3 + 1] = ry; sPos[r * 3 + 2] = rz;
        }
    }

    // ---- A tile (single pass, full K1) ----
    for (int i = tid; i < K1 * 128; i += 256) {
        int r = i / K1, k = i - r * K1;
        int row = row0 + r;
        float v = 0.f;
        if (row < n) {
            int sr = GATHER ? gidx[row] : row;
            v = in[(size_t)sr * K1 + k];
        }
        sA[k * RS + r] = v;
    }
    __syncthreads();   // covers weight/rel loads too

    unsigned long long acc[8][2];
    #pragma unroll
    for (int r = 0; r < 8; r++) { acc[r][0] = 0ULL; acc[r][1] = 0ULL; }

    #pragma unroll 8
    for (int k = 0; k < K1; k++) {
        const float4 av0 = *reinterpret_cast<const float4*>(&sA[k * RS + ty * 8]);
        const float4 av1 = *reinterpret_cast<const float4*>(&sA[k * RS + ty * 8 + 4]);
        const ulonglong2 bv = *reinterpret_cast<const ulonglong2*>(&sW1[k * 64 + tx * 4]);
        unsigned long long a0 = dup2(av0.x), a1 = dup2(av0.y), a2 = dup2(av0.z), a3 = dup2(av0.w);
        unsigned long long a4 = dup2(av1.x), a5 = dup2(av1.y), a6 = dup2(av1.z), a7 = dup2(av1.w);
        ffma2(acc[0][0], a0, bv.x); ffma2(acc[0][1], a0, bv.y);
        ffma2(acc[1][0], a1, bv.x); ffma2(acc[1][1], a1, bv.y);
        ffma2(acc[2][0], a2, bv.x); ffma2(acc[2][1], a2, bv.y);
        ffma2(acc[3][0], a3, bv.x); ffma2(acc[3][1], a3, bv.y);
        ffma2(acc[4][0], a4, bv.x); ffma2(acc[4][1], a4, bv.y);
        ffma2(acc[5][0], a5, bv.x); ffma2(acc[5][1], a5, bv.y);
        ffma2(acc[6][0], a6, bv.x); ffma2(acc[6][1], a6, bv.y);
        ffma2(acc[7][0], a7, bv.x); ffma2(acc[7][1], a7, bv.y);
    }

    // ---- epilogue 1 ----
    float v[8][4];
    const float b1x = b1[tx * 4], b1y = b1[tx * 4 + 1], b1z = b1[tx * 4 + 2], b1w = b1[tx * 4 + 3];
    #pragma unroll
    for (int r = 0; r < 8; r++) {
        float2 p0 = up2(acc[r][0]), p1 = up2(acc[r][1]);
        v[r][0] = p0.x + b1x; v[r][1] = p0.y + b1y;
        v[r][2] = p1.x + b1z; v[r][3] = p1.y + b1w;
        if (REL1) {
            int lr = ty * 8 + r;
            float rx = sRel[lr * 3], ry = sRel[lr * 3 + 1], rz = sRel[lr * 3 + 2];
            #pragma unroll
            for (int c = 0; c < 4; c++) {
                int col = tx * 4 + c;
                v[r][c] += rx * sWr1[col] + ry * sWr1[64 + col] + rz * sWr1[128 + col];
            }
        }
        #pragma unroll
        for (int c = 0; c < 4; c++) v[r][c] = fmaxf(v[r][c], 0.f);
        int row = row0 + ty * 8 + r;
        if (row < n) {
            size_t base = (size_t)row * 64 + tx * 4;
            if (NRES >= 1) {
                const float4 r1 = *reinterpret_cast<const float4*>(&res1[base]);
                v[r][0] += r1.x; v[r][1] += r1.y; v[r][2] += r1.z; v[r][3] += r1.w;
            }
            if (NRES >= 2) {
                const float4 r2 = *reinterpret_cast<const float4*>(&res2[base]);
                v[r][0] += r2.x; v[r][1] += r2.y; v[r][2] += r2.z; v[r][3] += r2.w;
            }
            if (STORE1) {
                float4 o = { v[r][0], v[r][1], v[r][2], v[r][3] };
                *reinterpret_cast<float4*>(&out1[base]) = o;
            }
        } else {
            v[r][0] = v[r][1] = v[r][2] = v[r][3] = 0.f;
        }
    }

    if (FUSE == 0) return;

    // ---- second GEMM: stage full v tile + full W2, one sync ----
    __syncthreads();   // all readers of sA done
    #pragma unroll
    for (int c = 0; c < 4; c++)
        #pragma unroll
        for (int r = 0; r < 8; r++)
            sA[(tx * 4 + c) * RS + (ty * 8 + r)] = v[r][c];
    if (FUSE == 1)
        for (int i = tid; i < 4096; i += 256) sW2[i] = W2[i];
    __syncthreads();

    if (FUSE == 1) {
        unsigned long long acc2[8][2];
        #pragma unroll
        for (int r = 0; r < 8; r++) { acc2[r][0] = 0ULL; acc2[r][1] = 0ULL; }
        #pragma unroll 8
        for (int k = 0; k < 64; k++) {
            const float4 av0 = *reinterpret_cast<const float4*>(&sA[k * RS + ty * 8]);
            const float4 av1 = *reinterpret_cast<const float4*>(&sA[k * RS + ty * 8 + 4]);
            const ulonglong2 bv = *reinterpret_cast<const ulonglong2*>(&sW2[k * 64 + tx * 4]);
            unsigned long long a0 = dup2(av0.x), a1 = dup2(av0.y), a2 = dup2(av0.z), a3 = dup2(av0.w);
            unsigned long long a4 = dup2(av1.x), a5 = dup2(av1.y), a6 = dup2(av1.z), a7 = dup2(av1.w);
            ffma2(acc2[0][0], a0, bv.x); ffma2(acc2[0][1], a0, bv.y);
            ffma2(acc2[1][0], a1, bv.x); ffma2(acc2[1][1], a1, bv.y);
            ffma2(acc2[2][0], a2, bv.x); ffma2(acc2[2][1], a2, bv.y);
            ffma2(acc2[3][0], a3, bv.x); ffma2(acc2[3][1], a3, bv.y);
            ffma2(acc2[4][0], a4, bv.x); ffma2(acc2[4][1], a4, bv.y);
            ffma2(acc2[5][0], a5, bv.x); ffma2(acc2[5][1], a5, bv.y);
            ffma2(acc2[6][0], a6, bv.x); ffma2(acc2[6][1], a6, bv.y);
            ffma2(acc2[7][0], a7, bv.x); ffma2(acc2[7][1], a7, bv.y);
        }
        const float b2x = b2[tx * 4], b2y = b2[tx * 4 + 1], b2z = b2[tx * 4 + 2], b2w = b2[tx * 4 + 3];
        #pragma unroll
        for (int r = 0; r < 8; r++) {
            int row = row0 + ty * 8 + r;
            if (row >= n) continue;
            float2 p0 = up2(acc2[r][0]), p1 = up2(acc2[r][1]);
            float w0 = p0.x + b2x, w1 = p0.y + b2y, w2 = p1.x + b2z, w3 = p1.y + b2w;
            if (REL2) {
                int lr = ty * 8 + r;
                const float* sv = REL2POS ? sPos : sRel;
                float rx = sv[lr * 3], ry = sv[lr * 3 + 1], rz = sv[lr * 3 + 2];
                int col = tx * 4;
                w0 += rx * sWr2[col]     + ry * sWr2[64 + col]     + rz * sWr2[128 + col];
                w1 += rx * sWr2[col + 1] + ry * sWr2[64 + col + 1] + rz * sWr2[128 + col + 1];
                w2 += rx * sWr2[col + 2] + ry * sWr2[64 + col + 2] + rz * sWr2[128 + col + 2];
                w3 += rx * sWr2[col + 3] + ry * sWr2[64 + col + 3] + rz * sWr2[128 + col + 3];
            }
            if (RELU2) {
                w0 = fmaxf(w0, 0.f); w1 = fmaxf(w1, 0.f);
                w2 = fmaxf(w2, 0.f); w3 = fmaxf(w3, 0.f);
            }
            if (H2OUT) {
                __half2 h0 = __floats2half2_rn(w0, w1);
                __half2 h1 = __floats2half2_rn(w2, w3);
                uint2 o;
                o.x = *reinterpret_cast<unsigned*>(&h0);
                o.y = *reinterpret_cast<unsigned*>(&h1);
                reinterpret_cast<uint2*>(out2)[(size_t)row * 16 + tx] = o;
            } else {
                float4 o = { w0, w1, w2, w3 };
                *reinterpret_cast<float4*>(reinterpret_cast<float*>(out2) + (size_t)row * 64 + tx * 4) = o;
            }
        }
    } else {
        // classifier: out2[row][cls] = sum_k tile[row][k] * W2[k*8+cls] + b2[cls]
        int r8 = tid >> 3, cls = tid & 7;
        #pragma unroll
        for (int h = 0; h < 4; h++) {
            int lr = r8 + h * 32;
            float a = b2[cls];
            #pragma unroll 16
            for (int k = 0; k < 64; k++)
                a = fmaf(sA[k * RS + lr], sW2[k * 8 + cls], a);
            int row = row0 + lr;
            if (row < n) reinterpret_cast<float*>(out2)[(size_t)row * 8 + cls] = a;
        }
    }
}

// ---------------- host orchestration ----------------
constexpr int GEMM_DSMEM = 64 * 132 * (int)sizeof(float);   // 33792 B

extern "C" void kernel_launch(void* const* d_in, const int* in_sizes, int n_in,
                              void* d_out, int out_size) {
    (void)in_sizes; (void)n_in; (void)out_size;
    float* A = nullptr;
    cudaGetSymbolAddress((void**)&A, g_arena);

    // one-time init (first call is the eager correctness run — never during capture)
    static cudaStream_t s2 = nullptr;
    static cudaEvent_t evFork = nullptr, evJoin = nullptr;
    if (!s2) {
        cudaStreamCreateWithFlags(&s2, cudaStreamNonBlocking);
        cudaEventCreateWithFlags(&evFork, cudaEventDisableTiming);
        cudaEventCreateWithFlags(&evJoin, cudaEventDisableTiming);
        auto setA = [](const void* f) {
            cudaFuncSetAttribute(f, cudaFuncAttributeMaxDynamicSharedMemorySize, GEMM_DSMEM);
        };
        setA((const void*)k_gemm<4,  false, true,  true,  0, true, 1, true, true,  false, true>);
        setA((const void*)k_gemm<64, false, false, false, 1, true, 1, true, true,  false, true>);
        setA((const void*)k_gemm<64, false, false, false, 1, true, 1, true, false, true,  false>);
        setA((const void*)k_gemm<64, false, false, false, 0, true, 1, true, true,  false, true>);
        setA((const void*)k_gemm<64, true,  false, true,  0, true, 1, true, true,  false, true>);
        setA((const void*)k_gemm<64, false, false, false, 1, true, 0, false, false, false, false>);
        setA((const void*)k_gemm<64, false, false, false, 2, true, 1, true, true,  false, true>);
        setA((const void*)k_gemm<64, false, false, false, 2, false, 2, false, false, false, false>);
    }

    float* f1   = A + OFF_F1;
    float* f2   = A + OFF_F2;
    float* f21  = A + OFF_F21;
    float* f5   = A + OFF_F5;
    float* f6   = A + OFF_F6;
    float* np   = A + OFF_NP;
    float* agg  = A + OFF_AGG;
    float* rel  = A + OFF_REL;
    float* mA   = A + OFF_MA;
    float* mB   = A + OFF_MB;
    float* mnp  = A + OFF_MNP;
    float* magg = A + OFF_MAGG;
    int* cnt0  = (int*)(A + OFF_CNT0);
    int* cnt1  = (int*)(A + OFF_CNT1);
    int* cntL  = (int*)(A + OFF_CNTL);
    int* offs0 = (int*)(A + OFF_OFFS0);
    int* cur0  = (int*)(A + OFF_CUR0);
    int* csr0  = (int*)(A + OFF_CSR0);
    int* offs1 = (int*)(A + OFF_OFFS1);
    int* cur1  = (int*)(A + OFF_CUR1);
    int* csr1  = (int*)(A + OFF_CSR1);
    int* offsL = (int*)(A + OFF_OFFSL);
    int* curL  = (int*)(A + OFF_CURL);
    int* csrL  = (int*)(A + OFF_CSRL);
    int* bsum  = (int*)(A + OFF_BSUM);

    const float* features = (const float*)d_in[0];
    const float* points   = (const float*)d_in[1];
    const float* centers  = (const float*)d_in[2];
    const int*   l0       = (const int*)d_in[3];
    const int*   l1       = (const int*)d_in[4];
    const int*   labels   = (const int*)d_in[5];
    const float* W_fe     = (const float*)d_in[6];
    const float* b_fe     = (const float*)d_in[7];
    const float* mini_We  = (const float*)d_in[8];
    const float* mini_be  = (const float*)d_in[9];
    const float* mini_Wu  = (const float*)d_in[10];
    const float* mini_bu  = (const float*)d_in[11];
    const float* W_m1     = (const float*)d_in[12];
    const float* b_m1     = (const float*)d_in[13];
    const float* W_m2     = (const float*)d_in[14];
    const float* b_m2     = (const float*)d_in[15];
    const float* gnn_We   = (const float*)d_in[16];
    const float* gnn_be   = (const float*)d_in[17];
    const float* gnn_Wu   = (const float*)d_in[18];
    const float* gnn_bu   = (const float*)d_in[19];
    const float* W_l      = (const float*)d_in[20];
    const float* b_l      = (const float*)d_in[21];
    const float* W_c      = (const float*)d_in[22];
    const float* b_c      = (const float*)d_in[23];
    float* out = (float*)d_out;

    const int TN = (Nn + 127) / 128;   // 782
    const int TM = (Mm + 127) / 128;   // 98

    const float* We0 = mini_We;               const float* be0 = mini_be;
    const float* We1 = mini_We + 67 * 64;     const float* be1 = mini_be + 64;
    const float* We2 = mini_We + 2 * 67 * 64; const float* be2 = mini_be + 128;
    const float* We3 = mini_We + 3 * 67 * 64; const float* be3 = mini_be + 192;
    const float* Wu0 = mini_Wu;               const float* bu0 = mini_bu;
    const float* Wu1 = mini_Wu + 4096;        const float* bu1 = mini_bu + 64;
    const float* Wu2 = mini_Wu + 2 * 4096;    const float* bu2 = mini_bu + 128;
    const float* Wu3 = mini_Wu + 3 * 4096;    const float* bu3 = mini_bu + 192;
    const float* gWe0 = gnn_We;               const float* gbe0 = gnn_be;
    const float* gWe1 = gnn_We + 67 * 64;     const float* gbe1 = gnn_be + 64;
    const float* gWu0 = gnn_Wu;               const float* gbu0 = gnn_bu;
    const float* gWu1 = gnn_Wu + 4096;        const float* gbu1 = gnn_bu + 64;

    // ---- fork: CSR build on s2, f1 GEMM on main stream ----
    cudaEventRecord(evFork, 0);
    cudaStreamWaitEvent(s2, evFork, 0);

    cudaMemsetAsync((void*)cnt0, 0, (OFF_OFFS0 - OFF_CNT0) * sizeof(float), s2);
    k_hist<<<(E0n + 255) / 256, 256, 0, s2>>>((const int2*)l0, cnt0, E0n);
    k_hist<<<(E1n + 255) / 256, 256, 0, s2>>>((const int2*)l1, cnt1, E1n);
    k_histL<<<(Nn + 255) / 256, 256, 0, s2>>>(labels, cntL, Nn);
    k_scanA<<<TOTB, 1024, 0, s2>>>(cnt0, offs0, cnt1, offs1, cntL, offsL, bsum);
    k_scanB<<<1, 96, 0, s2>>>(bsum, offs0, offs1, offsL);
    k_scanC<<<TOTB, 1024, 0, s2>>>(offs0, cur0, offs1, cur1, offsL, curL, bsum);
    k_scatter<<<(E0n + 255) / 256, 256, 0, s2>>>((const int2*)l0, cur0, csr0, E0n);
    k_scatter<<<(E1n + 255) / 256, 256, 0, s2>>>((const int2*)l1, cur1, csr1, E1n);
    k_scatterL<<<(Nn + 255) / 256, 256, 0, s2>>>(labels, curL, csrL, Nn);
    cudaEventRecord(evJoin, s2);

    // main stream: f1 = relu([feat,rel]@W_fe+b) ; t0(half) fused
    k_gemm<4, false, true, true, 0, true, 1, true, true, false, true><<<TN, 256, GEMM_DSMEM>>>(
        features, nullptr, points, centers, labels, rel, points,
        W_fe, b_fe, nullptr, nullptr, f1, We0 + 192, We0, be0, np, Nn);

    cudaStreamWaitEvent(0, evJoin, 0);

    // ---- GNN layer 0 on N ----
    k_agg<<<(Nn + 7) / 8, 256>>>(offs0, csr0, points, (const unsigned*)np, We0, (float2*)agg, Nn);
    k_gemm<64, false, false, false, 1, true, 1, true, true, false, true><<<TN, 256, GEMM_DSMEM>>>(
        agg, nullptr, nullptr, nullptr, nullptr, rel, points,
        Wu0, bu0, f1, nullptr, f2, We1 + 192, We1, be1, np, Nn);   // f2 ; t1(half)

    // ---- GNN layer 1 on N, fused with h = relu([f21,rel]@W_m1+b_m1) (h fp32) ----
    k_agg<<<(Nn + 7) / 8, 256>>>(offs0, csr0, points, (const unsigned*)np, We1, (float2*)agg, Nn);
    k_gemm<64, false, false, false, 1, true, 1, true, false, true, false><<<TN, 256, GEMM_DSMEM>>>(
        agg, nullptr, nullptr, nullptr, nullptr, rel, nullptr,
        Wu1, bu1, f2, nullptr, f21, W_m1, W_m1 + 4096, b_m1, np, Nn);   // f21 ; h (fp32)

    // ---- cluster branch ----
    k_segsum<<<(Mm + 7) / 8, 256>>>(offsL, csrL, (const float2*)np, (float2*)mA, Mm);
    k_gemm<64, false, false, false, 0, true, 1, true, true, false, true><<<TM, 256, GEMM_DSMEM>>>(
        mA, nullptr, nullptr, nullptr, nullptr, rel, centers,
        W_m2, b_m2, nullptr, nullptr, mB, gWe0 + 192, gWe0, gbe0, mnp, Mm);   // f3 ; tM0(half)
    k_agg<<<(Mm + 7) / 8, 256>>>(offs1, csr1, centers, (const unsigned*)mnp, gWe0, (float2*)magg, Mm);
    k_gemm<64, false, false, false, 1, true, 1, true, true, false, true><<<TM, 256, GEMM_DSMEM>>>(
        magg, nullptr, nullptr, nullptr, nullptr, rel, centers,
        gWu0, gbu0, mB, nullptr, mA, gWe1 + 192, gWe1, gbe1, mnp, Mm);        // f4 ; tM1(half)
    k_agg<<<(Mm + 7) / 8, 256>>>(offs1, csr1, centers, (const unsigned*)mnp, gWe1, (float2*)magg, Mm);
    k_gemm<64, false, false, false, 1, true, 0, false, false, false, false><<<TM, 256, GEMM_DSMEM>>>(
        magg, nullptr, nullptr, nullptr, nullptr, rel, nullptr,
        gWu1, gbu1, mA, nullptr, mB, nullptr, nullptr, nullptr, nullptr, Mm); // f4_1

    // ---- f5 = relu([f4_1[labels], rel]@W_l+b_l) ; t2(half) fused ----
    k_gemm<64, true, false, true, 0, true, 1, true, true, false, true><<<TN, 256, GEMM_DSMEM>>>(
        mB, labels, nullptr, nullptr, nullptr, rel, points,
        W_l, b_l, nullptr, nullptr, f5, We2 + 192, We2, be2, np, Nn);

    // ---- GNN layer 2 on N: f6 = relu(agg@Wu2+bu2)+f5+f21 ; t3(half) fused ----
    k_agg<<<(Nn + 7) / 8, 256>>>(offs0, csr0, points, (const unsigned*)np, We2, (float2*)agg, Nn);
    k_gemm<64, false, false, false, 2, true, 1, true, true, false, true><<<TN, 256, GEMM_DSMEM>>>(
        agg, nullptr, nullptr, nullptr, nullptr, rel, points,
        Wu2, bu2, f5, f21, f6, We3 + 192, We3, be3, np, Nn);

    // ---- GNN layer 3 on N fused with classifier ----
    k_agg<<<(Nn + 7) / 8, 256>>>(offs0, csr0, points, (const unsigned*)np, We3, (float2*)agg, Nn);
    k_gemm<64, false, false, false, 2, false, 2, false, false, false, false><<<TN, 256, GEMM_DSMEM>>>(
        agg, nullptr, nullptr, nullptr, nullptr, rel, nullptr,
        Wu3, bu3, f6, f2, nullptr, W_c, nullptr, b_c, out, Nn);
}